// round 6
// baseline (speedup 1.0000x reference)
#include <cuda_runtime.h>
#include <cstdint>

// ---------------------------------------------------------------------------
// starConvexLoss — R5: cp.async smem staging (coalesced DRAM), conflict-free
// LDS row reads, transposed partials for coalesced finalize. 2 launches.
// ---------------------------------------------------------------------------

#define C_DIM 10
#define TPB   256
#define SPG   32          // s-values per block  -> grid.y = S/SPG
#define MAXS  256
#define MAXBLK 256

#define CHUNK_FLOATS (TPB * 2 * C_DIM)      // 5120 floats = 20480 B per block-s
#define CHUNK_F4     (CHUNK_FLOATS / 4)     // 1280 float4

// partials laid out [blk][s] so k_final reads are coalesced across threads
static __device__ float g_pw [MAXBLK * MAXS];
static __device__ float g_pwt[MAXBLK * MAXS];
static __device__ float g_pn2[MAXBLK * MAXS];
static __device__ float g_pwstar[MAXBLK];

// ---- fast math --------------------------------------------------------------
__device__ __forceinline__ float ex2a(float x) {
    float r; asm("ex2.approx.f32 %0, %1;" : "=f"(r) : "f"(x)); return r;
}
__device__ __forceinline__ float lg2a(float x) {
    float r; asm("lg2.approx.f32 %0, %1;" : "=f"(r) : "f"(x)); return r;
}
__device__ __forceinline__ float rcpa(float x) {
    float r; asm("rcp.approx.f32 %0, %1;" : "=f"(r) : "f"(x)); return r;
}

// ---- packed f32x2 (Blackwell) -------------------------------------------------
typedef unsigned long long u64;
__device__ __forceinline__ u64 fma2(u64 a, u64 b, u64 c) {
    u64 d; asm("fma.rn.f32x2 %0, %1, %2, %3;" : "=l"(d) : "l"(a), "l"(b), "l"(c)); return d;
}
__device__ __forceinline__ u64 add2(u64 a, u64 b) {
    u64 d; asm("add.rn.f32x2 %0, %1, %2;" : "=l"(d) : "l"(a), "l"(b)); return d;
}
__device__ __forceinline__ u64 mul2(u64 a, u64 b) {
    u64 d; asm("mul.rn.f32x2 %0, %1, %2;" : "=l"(d) : "l"(a), "l"(b)); return d;
}
__device__ __forceinline__ u64 pk(float x, float y) {
    u64 d; asm("mov.b64 %0, {%1, %2};" : "=l"(d) : "f"(x), "f"(y)); return d;
}
__device__ __forceinline__ float2 upk(u64 v) {
    float2 f; asm("mov.b64 {%0, %1}, %2;" : "=f"(f.x), "=f"(f.y) : "l"(v)); return f;
}

// ---- cp.async ------------------------------------------------------------------
__device__ __forceinline__ void cpasync16(uint32_t saddr, const void* gaddr) {
    asm volatile("cp.async.cg.shared.global [%0], [%1], 16;" :: "r"(saddr), "l"(gaddr));
}
__device__ __forceinline__ void cpcommit() {
    asm volatile("cp.async.commit_group;");
}
template <int N>
__device__ __forceinline__ void cpwait() {
    asm volatile("cp.async.wait_group %0;" :: "n"(N));
}

#define KH   0.7213475204444817f     // 0.5 * log2(e)
#define L2E  1.4426950408889634f
#define LN2  0.6931471805599453f
#define EM1  1.7182818284590452f     // e - 1

// ---- per-row soft-CE core -------------------------------------------------------
__device__ __forceinline__ void rowCE(
    const u64 nvp[C_DIM / 2], const u64 lp[C_DIM / 2],
    float lpt, float ntc, u64& n2p, float& wr, float& wtr) {
    u64 sep = 0ull, dotp = 0ull, selp = 0ull, dotlp = 0ull;
    const u64 kh2 = pk(KH, KH);
    #pragma unroll
    for (int k = 0; k < C_DIM / 2; k++) {
        u64 xs = mul2(nvp[k], kh2);            // 0.5*log2(e)*n  (packed)
        float2 a = upk(xs);
        float eh0 = ex2a(a.x);                 // exp(0.5 n)
        float eh1 = ex2a(a.y);
        u64 ehp = pk(eh0, eh1);
        u64 ep  = mul2(ehp, ehp);              // exp(n)
        sep   = add2(sep, ep);
        dotp  = fma2(ep,  lp[k], dotp);
        selp  = add2(selp, ehp);
        dotlp = fma2(ehp, lp[k], dotlp);
        n2p   = fma2(nvp[k], nvp[k], n2p);
    }
    float2 v;
    v = upk(sep);   float se   = v.x + v.y;
    v = upk(dotp);  float dot  = v.x + v.y;
    v = upk(selp);  float sel  = v.x + v.y;
    v = upk(dotlp); float dotl = v.x + v.y;

    float eht = ex2a(ntc * KH);
    float et  = eht * eht;
    se   = fmaf(EM1, et,  se);   dot  = fmaf(EM1 * et,  lpt, dot);
    sel  = fmaf(EM1, eht, sel);  dotl = fmaf(EM1 * eht, lpt, dotl);

    float r = rcpa(se * sel);                  // one rcp serves both ratios
    wr  = dot  * sel * r;
    wtr = dotl * se  * r;
}

// ---- inline log-softmax of one pred row -----------------------------------------
__device__ __forceinline__ void rowLogp(
    const float* __restrict__ pred, int b, int t,
    u64 lp[C_DIM / 2], float& lpt) {
    float p[C_DIM];
    const float2* pr = (const float2*)pred + (size_t)b * (C_DIM / 2);
    #pragma unroll
    for (int k = 0; k < C_DIM / 2; k++) {
        float2 v = __ldg(pr + k); p[2 * k] = v.x; p[2 * k + 1] = v.y;
    }
    float m = p[0];
    #pragma unroll
    for (int c = 1; c < C_DIM; c++) m = fmaxf(m, p[c]);
    float sum = 0.f;
    #pragma unroll
    for (int c = 0; c < C_DIM; c++) sum += ex2a((p[c] - m) * L2E);
    float lse = fmaf(lg2a(sum), LN2, m);
    #pragma unroll
    for (int k = 0; k < C_DIM / 2; k++)
        lp[k] = pk(p[2 * k] - lse, p[2 * k + 1] - lse);
    lpt = __ldg(pred + (size_t)b * C_DIM + t) - lse;
}

// ---- main kernel -------------------------------------------------------------------
__global__ void __launch_bounds__(TPB, 4) k_main(
    const float* __restrict__ pred, const int* __restrict__ targets,
    const float* __restrict__ noise, int B, int S) {

    __shared__ float4 buf[2][CHUNK_F4];       // 40 KB double buffer
    __shared__ float  smr[2][3][TPB / 32];

    const int tid  = threadIdx.x;
    const int lane = tid & 31, w = tid >> 5;
    const int nPairs = B >> 1;

    int pi_raw = blockIdx.x * TPB + tid;      // global row-pair index
    float valid = (pi_raw < nPairs) ? 1.f : 0.f;
    int pi = min(pi_raw, nPairs - 1);
    int b0 = 2 * pi, b1 = b0 + 1;

    const int s0   = blockIdx.y * SPG;
    const int sEnd = min(s0 + SPG, S);

    int t0 = __ldg(targets + b0);
    int t1 = __ldg(targets + b1);

    u64 lp0[C_DIM / 2], lp1[C_DIM / 2];
    float lpt0, lpt1;
    rowLogp(pred, b0, t0, lp0, lpt0);
    rowLogp(pred, b1, t1, lp1, lpt1);

    // ---- wstar partial (only y==0 slice) ----
    if (blockIdx.y == 0) {
        float wp = -(lpt0 + lpt1) * valid;
        #pragma unroll
        for (int o = 16; o; o >>= 1) wp += __shfl_xor_sync(0xffffffffu, wp, o);
        if (lane == 0) smr[0][0][w] = wp;
        __syncthreads();
        if (w == 0) {
            float v = (lane < TPB / 32) ? smr[0][0][lane] : 0.f;
            #pragma unroll
            for (int o = 4; o; o >>= 1) v += __shfl_xor_sync(0xffffffffu, v, o);
            if (lane == 0) g_pwstar[blockIdx.x] = v;
        }
        __syncthreads();
    }

    // ---- cp.async staging: block chunk = CHUNK_F4 contiguous float4 per s ----
    const size_t sStride4 = (size_t)B * C_DIM / 4;                 // float4 per s
    const size_t chunk0   = (size_t)blockIdx.x * CHUNK_F4;         // block offset
    const float4* nbase4  = (const float4*)noise;
    const size_t total4   = (size_t)S * sStride4;

    // prologue: load s0 into buf[0]
    {
        const float4* src = nbase4 + (size_t)s0 * sStride4 + chunk0;
        #pragma unroll
        for (int j = 0; j < CHUNK_F4 / TPB; j++) {
            size_t gi = (size_t)s0 * sStride4 + chunk0 + tid + j * TPB;
            const float4* g = (gi < total4) ? (src + tid + j * TPB) : nbase4;
            cpasync16((uint32_t)__cvta_generic_to_shared(&buf[0][tid + j * TPB]), g);
        }
        cpcommit();
    }

    const int rowOff = tid * 5;                 // float4 offset of this thread's pair
    const int fOff   = tid * 20;                // float offset

    for (int s = s0; s < sEnd; s++) {
        int par = (s - s0) & 1;

        if (s + 1 < sEnd) {
            const float4* src = nbase4 + (size_t)(s + 1) * sStride4 + chunk0;
            #pragma unroll
            for (int j = 0; j < CHUNK_F4 / TPB; j++) {
                size_t gi = (size_t)(s + 1) * sStride4 + chunk0 + tid + j * TPB;
                const float4* g = (gi < total4) ? (src + tid + j * TPB) : nbase4;
                cpasync16((uint32_t)__cvta_generic_to_shared(&buf[par ^ 1][tid + j * TPB]), g);
            }
            cpcommit();
            cpwait<1>();      // buf[par] complete
        } else {
            cpwait<0>();
        }
        __syncthreads();      // make all threads' copies visible

        // conflict-free LDS.128: stride 20 banks covers all 32 banks per phase
        float4 q0 = buf[par][rowOff + 0];
        float4 q1 = buf[par][rowOff + 1];
        float4 q2 = buf[par][rowOff + 2];
        float4 q3 = buf[par][rowOff + 3];
        float4 q4 = buf[par][rowOff + 4];
        const float* fb = (const float*)buf[par];
        float nt0 = fb[fOff + t0];
        float nt1 = fb[fOff + 10 + t1];

        u64 n2p = 0ull;
        u64 nv[5];
        nv[0] = pk(q0.x, q0.y); nv[1] = pk(q0.z, q0.w);
        nv[2] = pk(q1.x, q1.y); nv[3] = pk(q1.z, q1.w);
        nv[4] = pk(q2.x, q2.y);
        float w0, wt0;
        rowCE(nv, lp0, lpt0, nt0, n2p, w0, wt0);

        nv[0] = pk(q2.z, q2.w);
        nv[1] = pk(q3.x, q3.y); nv[2] = pk(q3.z, q3.w);
        nv[3] = pk(q4.x, q4.y); nv[4] = pk(q4.z, q4.w);
        float w1, wt1;
        rowCE(nv, lp1, lpt1, nt1, n2p, w1, wt1);

        float2 nn = upk(n2p);
        float wr  = (w0  + w1 ) * valid;
        float wtr = (wt0 + wt1) * valid;
        float n2r = (nn.x + nn.y) * valid;

        // block reduce; the barrier also protects buf[par] for reuse at s+2
        #pragma unroll
        for (int o = 16; o; o >>= 1) {
            wr  += __shfl_xor_sync(0xffffffffu, wr,  o);
            wtr += __shfl_xor_sync(0xffffffffu, wtr, o);
            n2r += __shfl_xor_sync(0xffffffffu, n2r, o);
        }
        if (lane == 0) { smr[par][0][w] = wr; smr[par][1][w] = wtr; smr[par][2][w] = n2r; }
        __syncthreads();
        if (w == 0) {
            float va = (lane < TPB / 32) ? smr[par][0][lane] : 0.f;
            float vb = (lane < TPB / 32) ? smr[par][1][lane] : 0.f;
            float vc = (lane < TPB / 32) ? smr[par][2][lane] : 0.f;
            #pragma unroll
            for (int o = 4; o; o >>= 1) {
                va += __shfl_xor_sync(0xffffffffu, va, o);
                vb += __shfl_xor_sync(0xffffffffu, vb, o);
                vc += __shfl_xor_sync(0xffffffffu, vc, o);
            }
            if (lane == 0) {
                int idx = blockIdx.x * MAXS + s;        // [blk][s] layout
                g_pw [idx] = va;
                g_pwt[idx] = vb;
                g_pn2[idx] = vc;
            }
        }
    }
}

// ---- finalize: coalesced partial reduction + fp64 combine ---------------------------
__global__ void __launch_bounds__(128) k_final(
    float* __restrict__ out, int B, int S, int nblk) {
    int tid = threadIdx.x;
    __shared__ double sdw;
    __shared__ double sred[4];
    __shared__ double tmp[4];

    // wstar = sum of per-block partials / B
    {
        float wp = (tid < nblk) ? g_pwstar[tid] : 0.f;
        for (int j = tid + 128; j < nblk; j += 128) wp += g_pwstar[j];
        double d = (double)wp;
        #pragma unroll
        for (int o = 16; o; o >>= 1) d += __shfl_xor_sync(0xffffffffu, d, o);
        if ((tid & 31) == 0) tmp[tid >> 5] = d;
        __syncthreads();
        if (tid == 0) sdw = (tmp[0] + tmp[1] + tmp[2] + tmp[3]) / (double)B;
        __syncthreads();
    }
    double invB = 1.0 / (double)B;
    double wstar = sdw;

    double acc = 0.0;
    if (tid < S) {
        // partials are [blk][s]: consecutive threads (s) -> coalesced loads
        float sw = 0.f, swt = 0.f, sn2 = 0.f;
        #pragma unroll 8
        for (int blk = 0; blk < nblk; blk++) {
            int idx = blk * MAXS + tid;
            sw  += g_pw [idx];
            swt += g_pwt[idx];
            sn2 += g_pn2[idx];
        }
        double wv  = -(double)sw  * invB;
        double wtv = -(double)swt * invB;
        double n2  = (double)sn2;
        double sc1 = fmax(wstar - wtv, 0.0);
        double sc2 = fmax(wstar - wv + 0.05 * n2, 0.0);                      // MU*n2/2
        double sc3 = fmax(wtv - 0.5 * wstar + 0.5 * wv + 0.0125 * n2, 0.0);  // MU*LAM*(1-LAM)/2
        acc = sc1 + sc2 + sc3;
    }
    #pragma unroll
    for (int o = 16; o; o >>= 1) acc += __shfl_xor_sync(0xffffffffu, acc, o);
    if ((tid & 31) == 0) sred[tid >> 5] = acc;
    __syncthreads();
    if (tid == 0)
        out[0] = (float)(wstar + 0.05 * (sred[0] + sred[1] + sred[2] + sred[3]));  // RHO
}

// ---- launcher -------------------------------------------------------------------------
extern "C" void kernel_launch(void* const* d_in, const int* in_sizes, int n_in,
                              void* d_out, int out_size) {
    const float* pred    = (const float*)d_in[0];
    const int*   targets = (const int*)d_in[1];
    const float* noise   = (const float*)d_in[2];
    float* out = (float*)d_out;

    int B = in_sizes[1];                       // 65536
    int S = in_sizes[2] / in_sizes[0];         // 128

    int nPairs = B / 2;
    int gx = (nPairs + TPB - 1) / TPB;         // 128
    int gy = (S + SPG - 1) / SPG;              // 4
    dim3 grid(gx, gy);
    k_main<<<grid, TPB>>>(pred, targets, noise, B, S);
    k_final<<<1, 128>>>(out, B, S, gx);
}

// round 7
// speedup vs baseline: 1.3591x; 1.3591x over previous
#include <cuda_runtime.h>
#include <cstdint>

// ---------------------------------------------------------------------------
// starConvexLoss — R6: SINGLE kernel. cp.async staged loads, per-s atomic
// accumulators, fence+ticket last-block finalize (self-resetting for graph
// replay). No separate init/final launches.
// ---------------------------------------------------------------------------

#define C_DIM 10
#define TPB   256
#define SPG   16          // s-values per block  -> grid.y = S/SPG
#define MAXS  256

#define CHUNK_FLOATS (TPB * 2 * C_DIM)      // 5120 floats = 20480 B per block-s
#define CHUNK_F4     (CHUNK_FLOATS / 4)     // 1280 float4

// zero-initialized at load; reset by the finalizing block every run
static __device__ float g_Sw [MAXS];
static __device__ float g_Swt[MAXS];
static __device__ float g_Sn2[MAXS];
static __device__ float g_wstar;
static __device__ unsigned int g_done;

// ---- fast math --------------------------------------------------------------
__device__ __forceinline__ float ex2a(float x) {
    float r; asm("ex2.approx.f32 %0, %1;" : "=f"(r) : "f"(x)); return r;
}
__device__ __forceinline__ float lg2a(float x) {
    float r; asm("lg2.approx.f32 %0, %1;" : "=f"(r) : "f"(x)); return r;
}
__device__ __forceinline__ float rcpa(float x) {
    float r; asm("rcp.approx.f32 %0, %1;" : "=f"(r) : "f"(x)); return r;
}

// ---- packed f32x2 (Blackwell) -------------------------------------------------
typedef unsigned long long u64;
__device__ __forceinline__ u64 fma2(u64 a, u64 b, u64 c) {
    u64 d; asm("fma.rn.f32x2 %0, %1, %2, %3;" : "=l"(d) : "l"(a), "l"(b), "l"(c)); return d;
}
__device__ __forceinline__ u64 add2(u64 a, u64 b) {
    u64 d; asm("add.rn.f32x2 %0, %1, %2;" : "=l"(d) : "l"(a), "l"(b)); return d;
}
__device__ __forceinline__ u64 mul2(u64 a, u64 b) {
    u64 d; asm("mul.rn.f32x2 %0, %1, %2;" : "=l"(d) : "l"(a), "l"(b)); return d;
}
__device__ __forceinline__ u64 pk(float x, float y) {
    u64 d; asm("mov.b64 %0, {%1, %2};" : "=l"(d) : "f"(x), "f"(y)); return d;
}
__device__ __forceinline__ float2 upk(u64 v) {
    float2 f; asm("mov.b64 {%0, %1}, %2;" : "=f"(f.x), "=f"(f.y) : "l"(v)); return f;
}

// ---- cp.async ------------------------------------------------------------------
__device__ __forceinline__ void cpasync16(uint32_t saddr, const void* gaddr) {
    asm volatile("cp.async.cg.shared.global [%0], [%1], 16;" :: "r"(saddr), "l"(gaddr));
}
__device__ __forceinline__ void cpcommit() {
    asm volatile("cp.async.commit_group;");
}
template <int N>
__device__ __forceinline__ void cpwait() {
    asm volatile("cp.async.wait_group %0;" :: "n"(N));
}

#define KH   0.7213475204444817f     // 0.5 * log2(e)
#define L2E  1.4426950408889634f
#define LN2  0.6931471805599453f
#define EM1  1.7182818284590452f     // e - 1

// ---- per-row soft-CE core -------------------------------------------------------
__device__ __forceinline__ void rowCE(
    const u64 nvp[C_DIM / 2], const u64 lp[C_DIM / 2],
    float lpt, float ntc, u64& n2p, float& wr, float& wtr) {
    u64 sep = 0ull, dotp = 0ull, selp = 0ull, dotlp = 0ull;
    const u64 kh2 = pk(KH, KH);
    #pragma unroll
    for (int k = 0; k < C_DIM / 2; k++) {
        u64 xs = mul2(nvp[k], kh2);            // 0.5*log2(e)*n  (packed)
        float2 a = upk(xs);
        float eh0 = ex2a(a.x);                 // exp(0.5 n)
        float eh1 = ex2a(a.y);
        u64 ehp = pk(eh0, eh1);
        u64 ep  = mul2(ehp, ehp);              // exp(n)
        sep   = add2(sep, ep);
        dotp  = fma2(ep,  lp[k], dotp);
        selp  = add2(selp, ehp);
        dotlp = fma2(ehp, lp[k], dotlp);
        n2p   = fma2(nvp[k], nvp[k], n2p);
    }
    float2 v;
    v = upk(sep);   float se   = v.x + v.y;
    v = upk(dotp);  float dot  = v.x + v.y;
    v = upk(selp);  float sel  = v.x + v.y;
    v = upk(dotlp); float dotl = v.x + v.y;

    float eht = ex2a(ntc * KH);
    float et  = eht * eht;
    se   = fmaf(EM1, et,  se);   dot  = fmaf(EM1 * et,  lpt, dot);
    sel  = fmaf(EM1, eht, sel);  dotl = fmaf(EM1 * eht, lpt, dotl);

    float r = rcpa(se * sel);                  // one rcp serves both ratios
    wr  = dot  * sel * r;
    wtr = dotl * se  * r;
}

// ---- inline log-softmax of one pred row -----------------------------------------
__device__ __forceinline__ void rowLogp(
    const float* __restrict__ pred, int b, int t,
    u64 lp[C_DIM / 2], float& lpt) {
    float p[C_DIM];
    const float2* pr = (const float2*)pred + (size_t)b * (C_DIM / 2);
    #pragma unroll
    for (int k = 0; k < C_DIM / 2; k++) {
        float2 v = __ldg(pr + k); p[2 * k] = v.x; p[2 * k + 1] = v.y;
    }
    float m = p[0];
    #pragma unroll
    for (int c = 1; c < C_DIM; c++) m = fmaxf(m, p[c]);
    float sum = 0.f;
    #pragma unroll
    for (int c = 0; c < C_DIM; c++) sum += ex2a((p[c] - m) * L2E);
    float lse = fmaf(lg2a(sum), LN2, m);
    #pragma unroll
    for (int k = 0; k < C_DIM / 2; k++)
        lp[k] = pk(p[2 * k] - lse, p[2 * k + 1] - lse);
    lpt = __ldg(pred + (size_t)b * C_DIM + t) - lse;
}

// ---- the single fused kernel ------------------------------------------------------
__global__ void __launch_bounds__(TPB) k_all(
    const float* __restrict__ pred, const int* __restrict__ targets,
    const float* __restrict__ noise, float* __restrict__ out,
    int B, int S, unsigned int totalBlocks) {

    __shared__ float4 buf[2][CHUNK_F4];       // 40 KB double buffer
    __shared__ float  smr[2][3][TPB / 32];
    __shared__ unsigned int s_ticket;

    const int tid  = threadIdx.x;
    const int lane = tid & 31, w = tid >> 5;
    const int nPairs = B >> 1;

    int pi_raw = blockIdx.x * TPB + tid;      // global row-pair index
    float valid = (pi_raw < nPairs) ? 1.f : 0.f;
    int pi = min(pi_raw, nPairs - 1);
    int b0 = 2 * pi, b1 = b0 + 1;

    const int s0   = blockIdx.y * SPG;
    const int sEnd = min(s0 + SPG, S);

    int t0 = __ldg(targets + b0);
    int t1 = __ldg(targets + b1);

    // ---- prologue cp.async for s0 issued ASAP, before any compute ----
    const size_t sStride4 = (size_t)B * C_DIM / 4;                 // float4 per s
    const size_t chunk0   = (size_t)blockIdx.x * CHUNK_F4;         // block offset
    const float4* nbase4  = (const float4*)noise;
    const size_t total4   = (size_t)S * sStride4;
    {
        const float4* src = nbase4 + (size_t)s0 * sStride4 + chunk0;
        #pragma unroll
        for (int j = 0; j < CHUNK_F4 / TPB; j++) {
            size_t gi = (size_t)s0 * sStride4 + chunk0 + tid + j * TPB;
            const float4* g = (gi < total4) ? (src + tid + j * TPB) : nbase4;
            cpasync16((uint32_t)__cvta_generic_to_shared(&buf[0][tid + j * TPB]), g);
        }
        cpcommit();
    }

    u64 lp0[C_DIM / 2], lp1[C_DIM / 2];
    float lpt0, lpt1;
    rowLogp(pred, b0, t0, lp0, lpt0);
    rowLogp(pred, b1, t1, lp1, lpt1);

    // ---- wstar partial (only y==0 slice) ----
    if (blockIdx.y == 0) {
        float wp = -(lpt0 + lpt1) * valid;
        #pragma unroll
        for (int o = 16; o; o >>= 1) wp += __shfl_xor_sync(0xffffffffu, wp, o);
        if (lane == 0) smr[0][0][w] = wp;
        __syncthreads();
        if (w == 0) {
            float v = (lane < TPB / 32) ? smr[0][0][lane] : 0.f;
            #pragma unroll
            for (int o = 4; o; o >>= 1) v += __shfl_xor_sync(0xffffffffu, v, o);
            if (lane == 0) atomicAdd(&g_wstar, v);
        }
        __syncthreads();
    }

    const int rowOff = tid * 5;                 // float4 offset of this thread's pair
    const int fOff   = tid * 20;                // float offset

    for (int s = s0; s < sEnd; s++) {
        int par = (s - s0) & 1;

        if (s + 1 < sEnd) {
            const float4* src = nbase4 + (size_t)(s + 1) * sStride4 + chunk0;
            #pragma unroll
            for (int j = 0; j < CHUNK_F4 / TPB; j++) {
                size_t gi = (size_t)(s + 1) * sStride4 + chunk0 + tid + j * TPB;
                const float4* g = (gi < total4) ? (src + tid + j * TPB) : nbase4;
                cpasync16((uint32_t)__cvta_generic_to_shared(&buf[par ^ 1][tid + j * TPB]), g);
            }
            cpcommit();
            cpwait<1>();      // buf[par] complete
        } else {
            cpwait<0>();
        }
        __syncthreads();      // all copies of buf[par] visible

        // conflict-free LDS.128: stride of 20 banks covers all 32 banks per phase
        float4 q0 = buf[par][rowOff + 0];
        float4 q1 = buf[par][rowOff + 1];
        float4 q2 = buf[par][rowOff + 2];
        float4 q3 = buf[par][rowOff + 3];
        float4 q4 = buf[par][rowOff + 4];
        const float* fb = (const float*)buf[par];
        float nt0 = fb[fOff + t0];
        float nt1 = fb[fOff + 10 + t1];

        u64 n2p = 0ull;
        u64 nv[5];
        nv[0] = pk(q0.x, q0.y); nv[1] = pk(q0.z, q0.w);
        nv[2] = pk(q1.x, q1.y); nv[3] = pk(q1.z, q1.w);
        nv[4] = pk(q2.x, q2.y);
        float w0, wt0;
        rowCE(nv, lp0, lpt0, nt0, n2p, w0, wt0);

        nv[0] = pk(q2.z, q2.w);
        nv[1] = pk(q3.x, q3.y); nv[2] = pk(q3.z, q3.w);
        nv[3] = pk(q4.x, q4.y); nv[4] = pk(q4.z, q4.w);
        float w1, wt1;
        rowCE(nv, lp1, lpt1, nt1, n2p, w1, wt1);

        float2 nn = upk(n2p);
        float wr  = (w0  + w1 ) * valid;
        float wtr = (wt0 + wt1) * valid;
        float n2r = (nn.x + nn.y) * valid;

        #pragma unroll
        for (int o = 16; o; o >>= 1) {
            wr  += __shfl_xor_sync(0xffffffffu, wr,  o);
            wtr += __shfl_xor_sync(0xffffffffu, wtr, o);
            n2r += __shfl_xor_sync(0xffffffffu, n2r, o);
        }
        if (lane == 0) { smr[par][0][w] = wr; smr[par][1][w] = wtr; smr[par][2][w] = n2r; }
        __syncthreads();
        if (w == 0) {
            float va = (lane < TPB / 32) ? smr[par][0][lane] : 0.f;
            float vb = (lane < TPB / 32) ? smr[par][1][lane] : 0.f;
            float vc = (lane < TPB / 32) ? smr[par][2][lane] : 0.f;
            #pragma unroll
            for (int o = 4; o; o >>= 1) {
                va += __shfl_xor_sync(0xffffffffu, va, o);
                vb += __shfl_xor_sync(0xffffffffu, vb, o);
                vc += __shfl_xor_sync(0xffffffffu, vc, o);
            }
            if (lane == 0) {
                atomicAdd(&g_Sw[s],  va);
                atomicAdd(&g_Swt[s], vb);
                atomicAdd(&g_Sn2[s], vc);
            }
        }
    }

    // ---- fence + ticket: last block finalizes and resets state ----
    __threadfence();
    if (tid == 0) s_ticket = atomicAdd(&g_done, 1u);
    __syncthreads();
    if (s_ticket == totalBlocks - 1) {
        __threadfence();
        double invB = 1.0 / (double)B;
        double wstar = (double)(*(volatile float*)&g_wstar) * invB;

        double acc = 0.0;
        if (tid < S) {
            double wv  = -(double)(*(volatile float*)&g_Sw [tid]) * invB;
            double wtv = -(double)(*(volatile float*)&g_Swt[tid]) * invB;
            double n2  =  (double)(*(volatile float*)&g_Sn2[tid]);
            double sc1 = fmax(wstar - wtv, 0.0);
            double sc2 = fmax(wstar - wv + 0.05 * n2, 0.0);                      // MU*n2/2
            double sc3 = fmax(wtv - 0.5 * wstar + 0.5 * wv + 0.0125 * n2, 0.0);  // MU*LAM*(1-LAM)/2
            acc = sc1 + sc2 + sc3;
        }
        #pragma unroll
        for (int o = 16; o; o >>= 1) acc += __shfl_xor_sync(0xffffffffu, acc, o);
        __shared__ double sred[TPB / 32];
        if (lane == 0) sred[w] = acc;
        __syncthreads();
        if (tid == 0) {
            double t = 0.0;
            #pragma unroll
            for (int j = 0; j < TPB / 32; j++) t += sred[j];
            out[0] = (float)(wstar + 0.05 * t);          // RHO = 0.05
        }
        // reset persistent state for the next graph replay
        if (tid < MAXS) {
            *(volatile float*)&g_Sw [tid] = 0.f;
            *(volatile float*)&g_Swt[tid] = 0.f;
            *(volatile float*)&g_Sn2[tid] = 0.f;
        }
        if (tid == 0) {
            *(volatile float*)&g_wstar = 0.f;
            __threadfence();
            *(volatile unsigned int*)&g_done = 0u;
        }
    }
}

// ---- launcher -------------------------------------------------------------------------
extern "C" void kernel_launch(void* const* d_in, const int* in_sizes, int n_in,
                              void* d_out, int out_size) {
    const float* pred    = (const float*)d_in[0];
    const int*   targets = (const int*)d_in[1];
    const float* noise   = (const float*)d_in[2];
    float* out = (float*)d_out;

    int B = in_sizes[1];                       // 65536
    int S = in_sizes[2] / in_sizes[0];         // 128

    int nPairs = B / 2;
    int gx = (nPairs + TPB - 1) / TPB;         // 128
    int gy = (S + SPG - 1) / SPG;              // 8
    dim3 grid(gx, gy);
    k_all<<<grid, TPB>>>(pred, targets, noise, out, B, S, (unsigned)(gx * gy));
}